// round 9
// baseline (speedup 1.0000x reference)
#include <cuda_runtime.h>
#include <math.h>

// Problem constants (fixed by reference setup_inputs)
#define B_DIM 32
#define S_DIM 512
#define A_DIM 8
#define L_DIM 32
#define E_DIM 256
#define STILE 32
#define NBLK_X (S_DIM / STILE)          // 16
#define NBLK   (B_DIM * NBLK_X)         // 512
#define TAG_O 1

// Block partial sums: [conf_sum, cls_nll_sum, cls_count, reg_se_sum, pos_count]
__device__ float    g_part[NBLK][5];
__device__ unsigned g_count = 0;

__device__ __forceinline__ float ldcg_f(const float* p) {
    float v;
    asm volatile("ld.global.cg.f32 %0, [%1];" : "=f"(v) : "l"(p));
    return v;
}

// Consume one float4 quarter-row into its row exp-sum (8-lane subgroup reduce)
#define EXP_QUARTER(J, Q)                                                   \
    do {                                                                    \
        float e = (__expf((Q).x) + __expf((Q).y)) +                         \
                  (__expf((Q).z) + __expf((Q).w));                          \
        e += __shfl_xor_sync(0xffffffffu, e, 1);                            \
        e += __shfl_xor_sync(0xffffffffu, e, 2);                            \
        e += __shfl_xor_sync(0xffffffffu, e, 4);                            \
        if ((t & 7) == 0) s_sum[32 * (J) + sub] = e;                        \
    } while (0)

__global__ __launch_bounds__(256, 4)
void ssd_loss_fused(const int*   __restrict__ input_len,
                    const float* __restrict__ conf_logits,
                    const float* __restrict__ cls_logits,
                    const float* __restrict__ reg_logits,
                    const float* __restrict__ label,
                    const int*   __restrict__ index,
                    const float* __restrict__ anchors,
                    const float* __restrict__ thr_pos_p,
                    const float* __restrict__ thr_neg_p,
                    float*       __restrict__ out)
{
    const int b    = blockIdx.y;
    const int tile = blockIdx.x;
    const int t    = threadIdx.x;
    const int lane = t & 31;
    const int w    = t >> 5;
    const int sub  = t >> 3;

    __shared__ float2   s_ent[E_DIM];      // (ll, lr)
    __shared__ int      s_ty[E_DIM];
    __shared__ float    s_sum[256];        // per-row exp-sums
    __shared__ int      s_warp_cnt[8];
    __shared__ float    s_red[8][5];
    __shared__ unsigned s_ticket;

    // ---- Coalesced front-batched tile load: 8 x LDG.128 (512B contig per warp-instr) ----
    const int row0 = (b * S_DIM + tile * STILE) * A_DIM;
    const float4* gcls = (const float4*)cls_logits + (size_t)row0 * 8;
    const float4 d0 = gcls[t + 256 * 0];
    const float4 d1 = gcls[t + 256 * 1];
    const float4 d2 = gcls[t + 256 * 2];
    const float4 d3 = gcls[t + 256 * 3];
    const float4 d4 = gcls[t + 256 * 4];
    const float4 d5 = gcls[t + 256 * 5];
    const float4 d6 = gcls[t + 256 * 6];
    const float4 d7 = gcls[t + 256 * 7];

    // ---- Light loads (hoisted; label/index are all-CTA L2 hits) ----
    const float  x    = conf_logits[row0 + t];
    const float2 an   = ((const float2*)anchors)[tile * 256 + t];  // (center, size)
    const int    myix = index[t];
    const float  lty  = label[3 * t + 0];
    const float  lll  = label[3 * t + 1];
    const float  llr  = label[3 * t + 2];
    const int    len_b   = input_len[b];
    const float  thr_pos = thr_pos_p[0];
    const float  thr_neg = thr_neg_p[0];

    // ---- Consume each quarter-row immediately: registers die fast, no spills ----
    EXP_QUARTER(0, d0);
    EXP_QUARTER(1, d1);
    EXP_QUARTER(2, d2);
    EXP_QUARTER(3, d3);
    EXP_QUARTER(4, d4);
    EXP_QUARTER(5, d5);
    EXP_QUARTER(6, d6);
    EXP_QUARTER(7, d7);

    // ---- Order-preserving compaction of this batch's entities ----
    const int mine = (myix == b) ? 1 : 0;
    {
        const unsigned mask = __ballot_sync(0xffffffffu, mine);
        if (lane == 0) s_warp_cnt[w] = __popc(mask);
        __syncthreads();                       // also orders s_sum writes
        int base = 0;
        #pragma unroll
        for (int i = 0; i < 8; i++) if (i < w) base += s_warp_cnt[i];
        if (mine) {
            const int off = base + __popc(mask & ((1u << lane) - 1u));
            s_ty[off]  = (int)lty;
            s_ent[off] = make_float2(lll, llr);
        }
        __syncthreads();
    }
    int cnt = 0;
    #pragma unroll
    for (int i = 0; i < 8; i++) cnt += s_warp_cnt[i];

    const float ac  = an.x;
    const float asz = an.y;
    const float al  = ac - asz * 0.5f;
    const float ar  = ac + asz * 0.5f;
    const float rowsum = s_sum[t];

    // ---- IOU max / argmax (reference op order, strict > = first-max) ----
    float best = -1.0f;
    int   bk   = 0;
    for (int k = 0; k < cnt; k++) {
        const float2 e = s_ent[k];
        float inter = fminf(e.y, ar) - fmaxf(e.x, al);
        inter = fmaxf(inter, 0.0f);
        const float uni = (e.y - e.x) + (ar - al) - inter;
        const float iou = inter / uni;
        if (iou > best) { best = iou; bk = k; }
    }

    const int  s_idx  = tile * STILE + sub;
    const bool valid  = (s_idx < len_b);
    const bool active = valid && (cnt > 0);
    const bool pos    = active && (best >= thr_pos);
    const bool neg    = active && (best <= thr_neg);

    // ---- Confidence (BCE-with-logits, mean over ALL anchors) ----
    const float sp = fmaxf(x, 0.0f) + __logf(1.0f + __expf(-fabsf(x)));
    const float conf_term = sp - (pos ? x : 0.0f);

    // ---- Classification NLL (tv is an L1-hit scalar load from own row) ----
    float cls_nll = 0.0f, cls_c = 0.0f;
    if (pos || neg) {
        const int target = pos ? s_ty[bk] : TAG_O;
        const float tv = cls_logits[(size_t)(row0 + t) * L_DIM + target];
        cls_nll = -(tv - __logf(rowsum));
        cls_c   = 1.0f;
    }

    // ---- Regression SE on positives only ----
    float reg_se = 0.0f, pos_c = 0.0f;
    if (pos) {
        const float2 e = s_ent[bk];
        const float lc = (e.x + e.y) * 0.5f;
        const float ls = e.y - e.x;
        const float oc = (lc - ac) / asz;
        const float os = ls / asz;
        const float r0 = reg_logits[(size_t)(row0 + t) * 2 + 0];
        const float r1 = reg_logits[(size_t)(row0 + t) * 2 + 1];
        reg_se = (r0 - oc) * (r0 - oc) + (r1 - os) * (r1 - os);
        pos_c  = 1.0f;
    }

    // ---- Deterministic block reduction ----
    const int bid = b * NBLK_X + tile;
    {
        float vals[5] = {conf_term, cls_nll, cls_c, reg_se, pos_c};
        #pragma unroll
        for (int j = 0; j < 5; j++) {
            float v = vals[j];
            #pragma unroll
            for (int off = 16; off > 0; off >>= 1)
                v += __shfl_down_sync(0xffffffffu, v, off);
            if (lane == 0) s_red[w][j] = v;
        }
        __syncthreads();
        if (t < 5) {
            float acc = 0.0f;
            #pragma unroll
            for (int i = 0; i < 8; i++) acc += s_red[i][t];
            g_part[bid][t] = acc;
        }
    }

    // ---- Last-block-done final reduction (no second launch) ----
    __threadfence();
    __syncthreads();
    if (t == 0) s_ticket = atomicAdd(&g_count, 1u);
    __syncthreads();
    if (s_ticket != NBLK - 1) return;

    float acc[5];
    #pragma unroll
    for (int j = 0; j < 5; j++)
        acc[j] = ldcg_f(&g_part[t][j]) + ldcg_f(&g_part[t + 256][j]);

    #pragma unroll
    for (int j = 0; j < 5; j++) {
        float v = acc[j];
        #pragma unroll
        for (int off = 16; off > 0; off >>= 1)
            v += __shfl_down_sync(0xffffffffu, v, off);
        if (lane == 0) s_red[w][j] = v;
    }
    __syncthreads();
    if (t == 0) {
        float sums[5];
        #pragma unroll
        for (int j = 0; j < 5; j++) {
            float s = 0.0f;
            #pragma unroll
            for (int i = 0; i < 8; i++) s += s_red[i][j];
            sums[j] = s;
        }
        const float conf_loss = sums[0] / (float)(B_DIM * S_DIM * A_DIM);
        const float cls_loss  = sums[1] / sums[2];
        const float reg_loss  = sums[3] / (sums[4] * 2.0f);
        out[0] = conf_loss + cls_loss + reg_loss;
        out[1] = conf_loss;
        out[2] = cls_loss;
        out[3] = reg_loss;
        atomicExch(&g_count, 0u);   // reset for next graph replay
    }
}

extern "C" void kernel_launch(void* const* d_in, const int* in_sizes, int n_in,
                              void* d_out, int out_size)
{
    const int*   input_len   = (const int*)  d_in[0];
    const float* conf_logits = (const float*)d_in[1];
    const float* cls_logits  = (const float*)d_in[2];
    const float* reg_logits  = (const float*)d_in[3];
    const float* label       = (const float*)d_in[4];
    const int*   index       = (const int*)  d_in[5];
    const float* anchors     = (const float*)d_in[6];
    const float* thr_pos     = (const float*)d_in[7];
    const float* thr_neg     = (const float*)d_in[8];
    float* out = (float*)d_out;

    dim3 grid(NBLK_X, B_DIM);
    ssd_loss_fused<<<grid, 256>>>(input_len, conf_logits, cls_logits, reg_logits,
                                  label, index, anchors, thr_pos, thr_neg, out);
}

// round 10
// speedup vs baseline: 1.3750x; 1.3750x over previous
#include <cuda_runtime.h>
#include <math.h>

// Problem constants (fixed by reference setup_inputs)
#define B_DIM 32
#define S_DIM 512
#define A_DIM 8
#define L_DIM 32
#define E_DIM 256
#define STILE 32
#define NBLK_X (S_DIM / STILE)          // 16
#define NBLK   (B_DIM * NBLK_X)         // 512
#define TAG_O 1

// Block partial sums, transposed for coalesced final read:
// [conf_sum, cls_nll_sum, cls_count, reg_se_sum, pos_count] x NBLK
__device__ float    g_part[5][NBLK];
__device__ unsigned g_count = 0;

__device__ __forceinline__ float ldcg_f(const float* p) {
    float v;
    asm volatile("ld.global.cg.f32 %0, [%1];" : "=f"(v) : "l"(p));
    return v;
}

__global__ __launch_bounds__(256, 4)
void ssd_loss_fused(const int*   __restrict__ input_len,
                    const float* __restrict__ conf_logits,
                    const float* __restrict__ cls_logits,
                    const float* __restrict__ reg_logits,
                    const float* __restrict__ label,
                    const int*   __restrict__ index,
                    const float* __restrict__ anchors,
                    const float* __restrict__ thr_pos_p,
                    const float* __restrict__ thr_neg_p,
                    float*       __restrict__ out)
{
    const int b    = blockIdx.y;
    const int tile = blockIdx.x;
    const int t    = threadIdx.x;
    const int lane = t & 31;
    const int w    = t >> 5;
    const int sub  = t >> 3;     // row-within-32-group owned cooperatively
    const int q    = t & 7;      // quarter index

    __shared__ float    s_part[256][8];    // 8KB: per-(row, quarter) exp partials
    __shared__ float2   s_ent[E_DIM];      // (ll, lr)
    __shared__ int      s_ty[E_DIM];
    __shared__ int      s_warp_cnt[8];
    __shared__ float    s_red[8][5];
    __shared__ unsigned s_ticket;

    // ---- Coalesced front-batched tile load: 8 x LDG.128 (512B contig per warp-instr) ----
    const int row0 = (b * S_DIM + tile * STILE) * A_DIM;
    const float4* gcls = (const float4*)cls_logits + (size_t)row0 * 8;
    const float4 d0 = gcls[t + 256 * 0];
    const float4 d1 = gcls[t + 256 * 1];
    const float4 d2 = gcls[t + 256 * 2];
    const float4 d3 = gcls[t + 256 * 3];
    const float4 d4 = gcls[t + 256 * 4];
    const float4 d5 = gcls[t + 256 * 5];
    const float4 d6 = gcls[t + 256 * 6];
    const float4 d7 = gcls[t + 256 * 7];

    // ---- Light loads (all-CTA L2 hits for label/index/thresholds) ----
    const float  x    = conf_logits[row0 + t];
    const float2 an   = ((const float2*)anchors)[tile * 256 + t];  // (center, size)
    const int    myix = index[t];
    const float  lty  = label[3 * t + 0];
    const float  lll  = label[3 * t + 1];
    const float  llr  = label[3 * t + 2];
    const int    len_b   = input_len[b];
    const float  thr_pos = thr_pos_p[0];
    const float  thr_neg = thr_neg_p[0];

    // ---- Consume each quarter-row immediately; partials go to smem (no shuffles) ----
    // Thread t's j-th float4 is quarter q of row 32j+sub.
    {
        const float4 dd[8] = {d0, d1, d2, d3, d4, d5, d6, d7};
        #pragma unroll
        for (int j = 0; j < 8; j++) {
            const float4 p = dd[j];
            s_part[32 * j + sub][q] =
                (__expf(p.x) + __expf(p.y)) + (__expf(p.z) + __expf(p.w));
        }
    }

    // ---- Order-preserving compaction of this batch's entities ----
    const int mine = (myix == b) ? 1 : 0;
    const unsigned cmask = __ballot_sync(0xffffffffu, mine);
    if (lane == 0) s_warp_cnt[w] = __popc(cmask);
    __syncthreads();                           // orders s_part + warp counts

    // Row sum: read own row back (2 x LDS.128), reduce in-thread
    float rowsum;
    {
        const float4 r0 = *(const float4*)&s_part[t][0];
        const float4 r1 = *(const float4*)&s_part[t][4];
        rowsum = ((r0.x + r0.y) + (r0.z + r0.w)) + ((r1.x + r1.y) + (r1.z + r1.w));
    }
    const float logsum = __logf(rowsum);       // MUFU latency overlaps below

    int base = 0;
    #pragma unroll
    for (int i = 0; i < 8; i++) if (i < w) base += s_warp_cnt[i];
    if (mine) {
        const int off = base + __popc(cmask & ((1u << lane) - 1u));
        s_ty[off]  = (int)lty;
        s_ent[off] = make_float2(lll, llr);
    }
    __syncthreads();

    int cnt = 0;
    #pragma unroll
    for (int i = 0; i < 8; i++) cnt += s_warp_cnt[i];

    const float ac  = an.x;
    const float asz = an.y;
    const float al  = ac - asz * 0.5f;
    const float ar  = ac + asz * 0.5f;

    // ---- IOU max / argmax (reference op order, strict > = first-max) ----
    float best = -1.0f;
    int   bk   = 0;
    for (int k = 0; k < cnt; k++) {
        const float2 e = s_ent[k];
        float inter = fminf(e.y, ar) - fmaxf(e.x, al);
        inter = fmaxf(inter, 0.0f);
        const float uni = (e.y - e.x) + (ar - al) - inter;
        const float iou = inter / uni;
        if (iou > best) { best = iou; bk = k; }
    }

    const int  s_idx  = tile * STILE + sub;
    const bool valid  = (s_idx < len_b);
    const bool active = valid && (cnt > 0);
    const bool pos    = active && (best >= thr_pos);
    const bool neg    = active && (best <= thr_neg);

    // ---- Confidence (BCE-with-logits, mean over ALL anchors) ----
    const float sp = fmaxf(x, 0.0f) + __logf(1.0f + __expf(-fabsf(x)));
    const float conf_term = sp - (pos ? x : 0.0f);

    // ---- Classification NLL (tv is an L1-hit scalar load from own row) ----
    float cls_nll = 0.0f;
    if (pos || neg) {
        const int target = pos ? s_ty[bk] : TAG_O;
        const float tv = cls_logits[(size_t)(row0 + t) * L_DIM + target];
        cls_nll = -(tv - logsum);
    }

    // ---- Regression SE on positives only ----
    float reg_se = 0.0f;
    if (pos) {
        const float2 e = s_ent[bk];
        const float lc = (e.x + e.y) * 0.5f;
        const float ls = e.y - e.x;
        const float oc = (lc - ac) / asz;
        const float os = ls / asz;
        const float r0 = reg_logits[(size_t)(row0 + t) * 2 + 0];
        const float r1 = reg_logits[(size_t)(row0 + t) * 2 + 1];
        reg_se = (r0 - oc) * (r0 - oc) + (r1 - os) * (r1 - os);
    }

    // ---- Deterministic block reduction (3 float chains + 2 popc counts) ----
    const int bid = b * NBLK_X + tile;
    {
        const int cls_cnt_w = __popc(__ballot_sync(0xffffffffu, pos || neg));
        const int pos_cnt_w = __popc(__ballot_sync(0xffffffffu, pos));
        float vals[3] = {conf_term, cls_nll, reg_se};
        #pragma unroll
        for (int j = 0; j < 3; j++) {
            float v = vals[j];
            #pragma unroll
            for (int off = 16; off > 0; off >>= 1)
                v += __shfl_down_sync(0xffffffffu, v, off);
            vals[j] = v;
        }
        if (lane == 0) {
            s_red[w][0] = vals[0];
            s_red[w][1] = vals[1];
            s_red[w][2] = (float)cls_cnt_w;
            s_red[w][3] = vals[2];
            s_red[w][4] = (float)pos_cnt_w;
        }
        __syncthreads();
        if (t < 5) {
            float acc = 0.0f;
            #pragma unroll
            for (int i = 0; i < 8; i++) acc += s_red[i][t];
            g_part[t][bid] = acc;
        }
    }

    // ---- Last-block-done final reduction (no second launch) ----
    __threadfence();
    __syncthreads();
    if (t == 0) s_ticket = atomicAdd(&g_count, 1u);
    __syncthreads();
    if (s_ticket != NBLK - 1) return;

    float acc[5];
    #pragma unroll
    for (int j = 0; j < 5; j++)
        acc[j] = ldcg_f(&g_part[j][t]) + ldcg_f(&g_part[j][t + 256]);

    #pragma unroll
    for (int j = 0; j < 5; j++) {
        float v = acc[j];
        #pragma unroll
        for (int off = 16; off > 0; off >>= 1)
            v += __shfl_down_sync(0xffffffffu, v, off);
        if (lane == 0) s_red[w][j] = v;
    }
    __syncthreads();
    if (t == 0) {
        float sums[5];
        #pragma unroll
        for (int j = 0; j < 5; j++) {
            float s = 0.0f;
            #pragma unroll
            for (int i = 0; i < 8; i++) s += s_red[i][j];
            sums[j] = s;
        }
        const float conf_loss = sums[0] / (float)(B_DIM * S_DIM * A_DIM);
        const float cls_loss  = sums[1] / sums[2];
        const float reg_loss  = sums[3] / (sums[4] * 2.0f);
        out[0] = conf_loss + cls_loss + reg_loss;
        out[1] = conf_loss;
        out[2] = cls_loss;
        out[3] = reg_loss;
        atomicExch(&g_count, 0u);   // reset for next graph replay
    }
}

extern "C" void kernel_launch(void* const* d_in, const int* in_sizes, int n_in,
                              void* d_out, int out_size)
{
    const int*   input_len   = (const int*)  d_in[0];
    const float* conf_logits = (const float*)d_in[1];
    const float* cls_logits  = (const float*)d_in[2];
    const float* reg_logits  = (const float*)d_in[3];
    const float* label       = (const float*)d_in[4];
    const int*   index       = (const int*)  d_in[5];
    const float* anchors     = (const float*)d_in[6];
    const float* thr_pos     = (const float*)d_in[7];
    const float* thr_neg     = (const float*)d_in[8];
    float* out = (float*)d_out;

    dim3 grid(NBLK_X, B_DIM);
    ssd_loss_fused<<<grid, 256>>>(input_len, conf_logits, cls_logits, reg_logits,
                                  label, index, anchors, thr_pos, thr_neg, out);
}